// round 2
// baseline (speedup 1.0000x reference)
#include <cuda_runtime.h>
#include <math.h>

// ---------------------------------------------------------------------------
// Problem constants
// ---------------------------------------------------------------------------
#define BATCH   32
#define HRES    64
#define WRES    64
#define CDIM    256
#define WS      8
#define SHIFT   4
#define NH      8
#define NTOK    64          // WS*WS tokens per window
#define HD      32          // head dim
#define HID     1024        // mlp hidden
#define CPB_HID 512
#define MROWS   (BATCH * HRES * WRES)   // 131072 total token rows

// ---------------------------------------------------------------------------
// Scratch (allocation-free: __device__ globals)
// ---------------------------------------------------------------------------
__device__ float g_qkv[MROWS * 3 * CDIM];     // 402 MB
__device__ float g_attnout[MROWS * CDIM];     // 134 MB
__device__ float g_projimg[MROWS * CDIM];     // 134 MB
__device__ float g_x1[MROWS * CDIM];          // 134 MB
__device__ float g_h[MROWS * HID];            // 537 MB
__device__ float g_mlp[MROWS * CDIM];         // 134 MB
__device__ float g_bias_table[225 * NH];      // CPB MLP output per rel-pos
__device__ float g_rpb[NH * NTOK * NTOK];     // sigmoid(bias)*16, [h][i][j]

// ---------------------------------------------------------------------------
// shift+window permutation. Row t in window-token order <-> image row P(t).
// Gather for QKV input and scatter for proj output use the SAME index.
// ---------------------------------------------------------------------------
__device__ __forceinline__ int permrow(int t) {
    int b   = t >> 12;          // 4096 tokens per batch image
    int loc = t & 4095;
    int win = loc >> 6;
    int n   = loc & 63;
    int sh = ((win >> 3) << 3) + (n >> 3);   // shifted-frame row
    int sw = ((win & 7) << 3) + (n & 7);     // shifted-frame col
    int h = (sh + SHIFT) & 63;
    int w = (sw + SHIFT) & 63;
    return (b << 12) + (h << 6) + w;
}

// ---------------------------------------------------------------------------
// CPB table kernel: bias_table[p][h] for the 15x15 relative positions.
// One block per p.
// ---------------------------------------------------------------------------
__device__ __forceinline__ float cpb_feat(int v) {
    float tv = (float)v * (8.0f / 7.0f);
    float s  = (tv > 0.f) ? 1.f : ((tv < 0.f) ? -1.f : 0.f);
    return s * log2f(fabsf(tv) + 1.0f) * (1.0f / 3.0f);
}

__global__ __launch_bounds__(256)
void cpb_table_kernel(const float* __restrict__ w1, const float* __restrict__ b1,
                      const float* __restrict__ w2) {
    int p  = blockIdx.x;          // 0..224
    int iy = p / 15, ix = p % 15;
    float fy = cpb_feat(iy - 7);
    float fx = cpb_feat(ix - 7);
    int t = threadIdx.x;
    float acc[NH];
#pragma unroll
    for (int hh = 0; hh < NH; ++hh) acc[hh] = 0.f;
    for (int j = t; j < CPB_HID; j += 256) {
        float hmid = fy * w1[2 * j] + fx * w1[2 * j + 1] + b1[j];
        hmid = fmaxf(hmid, 0.f);
#pragma unroll
        for (int hh = 0; hh < NH; ++hh) acc[hh] += hmid * w2[hh * CPB_HID + j];
    }
    __shared__ float red[256];
    for (int hh = 0; hh < NH; ++hh) {
        red[t] = acc[hh];
        __syncthreads();
        for (int s = 128; s > 0; s >>= 1) {
            if (t < s) red[t] += red[t + s];
            __syncthreads();
        }
        if (t == 0) g_bias_table[p * NH + hh] = red[0];
        __syncthreads();
    }
}

// rpb[h][i][j] = sigmoid(bias_table[rel(i,j)][h]) * 16
__global__ __launch_bounds__(256)
void rpb_kernel() {
    int idx = blockIdx.x * 256 + threadIdx.x;      // 8*64*64 = 32768
    if (idx >= NH * NTOK * NTOK) return;
    int h   = idx >> 12;
    int rem = idx & 4095;
    int i = rem >> 6, j = rem & 63;
    int ri = i >> 3, ci = i & 7, rj = j >> 3, cj = j & 7;
    int p = (ri - rj + 7) * 15 + (ci - cj + 7);
    float v = g_bias_table[p * NH + h];
    g_rpb[idx] = 16.0f / (1.0f + expf(-v));
}

// ---------------------------------------------------------------------------
// SGEMM: C[M,N] = A[M,K] @ W[N,K]^T + bias, optional row remaps & activation.
// 128x128 block tile, BK=8, 256 threads, 8x8 per thread.
// RA: 1 -> A row index permuted (window gather).  RC: 1 -> C row scattered.
// BIASM: 0 -> bias0[n];  1 -> qkv concat bias (q_bias | 0 | v_bias)
// ACT: 0 none, 1 exact GELU
// ---------------------------------------------------------------------------
template <int RA, int RC, int BIASM, int ACT>
__global__ __launch_bounds__(256)
void sgemm_kernel(const float* __restrict__ A, const float* __restrict__ W,
                  const float* __restrict__ b0, const float* __restrict__ b1,
                  float* __restrict__ C, int M, int N, int K) {
    __shared__ float As[8][132];
    __shared__ float Bs[8][132];
    const int tid  = threadIdx.x;
    const int brow = blockIdx.y * 128;
    const int bcol = blockIdx.x * 128;
    const int lr = tid >> 1;            // 0..127
    const int lk = (tid & 1) << 2;      // 0 or 4
    int arow = brow + lr;
    if (RA == 1) arow = permrow(arow);
    const float* Ap = A + (size_t)arow * K + lk;
    const float* Wp = W + (size_t)(bcol + lr) * K + lk;
    const int ty = tid >> 4, tx = tid & 15;
    const int rm = ty << 3, rn = tx << 3;
    float acc[8][8];
#pragma unroll
    for (int i = 0; i < 8; ++i)
#pragma unroll
        for (int j = 0; j < 8; ++j) acc[i][j] = 0.f;

    for (int kt = 0; kt < K; kt += 8) {
        float4 av = *reinterpret_cast<const float4*>(Ap + kt);
        float4 wv = *reinterpret_cast<const float4*>(Wp + kt);
        __syncthreads();
        As[lk + 0][lr] = av.x; As[lk + 1][lr] = av.y;
        As[lk + 2][lr] = av.z; As[lk + 3][lr] = av.w;
        Bs[lk + 0][lr] = wv.x; Bs[lk + 1][lr] = wv.y;
        Bs[lk + 2][lr] = wv.z; Bs[lk + 3][lr] = wv.w;
        __syncthreads();
#pragma unroll
        for (int k = 0; k < 8; ++k) {
            float a[8], bb[8];
            *reinterpret_cast<float4*>(a)      = *reinterpret_cast<const float4*>(&As[k][rm]);
            *reinterpret_cast<float4*>(a + 4)  = *reinterpret_cast<const float4*>(&As[k][rm + 4]);
            *reinterpret_cast<float4*>(bb)     = *reinterpret_cast<const float4*>(&Bs[k][rn]);
            *reinterpret_cast<float4*>(bb + 4) = *reinterpret_cast<const float4*>(&Bs[k][rn + 4]);
#pragma unroll
            for (int i = 0; i < 8; ++i)
#pragma unroll
                for (int j = 0; j < 8; ++j) acc[i][j] += a[i] * bb[j];
        }
    }

#pragma unroll
    for (int i = 0; i < 8; ++i) {
        int crow = brow + rm + i;
        if (RC == 1) crow = permrow(crow);
        float* Cp = C + (size_t)crow * N + bcol + rn;
#pragma unroll
        for (int j = 0; j < 8; ++j) {
            int n = bcol + rn + j;
            float bv;
            if (BIASM == 0) {
                bv = b0[n];
            } else {
                bv = (n < 256) ? b0[n] : ((n < 512) ? 0.f : b1[n - 512]);
            }
            float v = acc[i][j] + bv;
            if (ACT == 1) v = 0.5f * v * (1.0f + erff(v * 0.70710678118654752f));
            Cp[j] = v;
        }
    }
}

// ---------------------------------------------------------------------------
// Fused window attention: one block per (window, head). 256 threads.
// cosine attention (l2norm q,k), clamped exp(logit_scale), +rpb, +shift mask,
// softmax, AV. Output in [t, nh*HD + hd] layout.
// ---------------------------------------------------------------------------
__global__ __launch_bounds__(256)
void attn_kernel(const float* __restrict__ qkv, const float* __restrict__ logit_scale,
                 float* __restrict__ out) {
    __shared__ float qs[NTOK * 33];
    __shared__ float ks[NTOK * 33];
    __shared__ float vs[NTOK * 33];
    __shared__ float at[NTOK * 65];
    __shared__ int   grp[NTOK];

    const int blk = blockIdx.x;
    const int win = blk >> 3;
    const int h   = blk & 7;
    const int tid = threadIdx.x;
    const int t0  = win << 6;

    // load q/k/v tiles: 3 * 64 * 32 floats = 1536 float4
    for (int e4 = tid; e4 < 1536; e4 += 256) {
        int tensor = e4 >> 9;
        int rem = e4 & 511;
        int n = rem >> 3;
        int hd4 = rem & 7;
        float4 val = *reinterpret_cast<const float4*>(
            qkv + (size_t)(t0 + n) * 768 + tensor * 256 + h * 32 + (hd4 << 2));
        float* dst = (tensor == 0 ? qs : (tensor == 1 ? ks : vs)) + n * 33 + (hd4 << 2);
        dst[0] = val.x; dst[1] = val.y; dst[2] = val.z; dst[3] = val.w;
    }
    __syncthreads();

    // l2-normalize q rows / k rows; compute shift-mask groups
    if (tid < 64) {
        float ss = 0.f;
#pragma unroll
        for (int d = 0; d < 32; ++d) { float x = qs[tid * 33 + d]; ss += x * x; }
        float inv = 1.0f / fmaxf(sqrtf(ss), 1e-12f);
#pragma unroll
        for (int d = 0; d < 32; ++d) qs[tid * 33 + d] *= inv;
    } else if (tid < 128) {
        int r = tid - 64;
        float ss = 0.f;
#pragma unroll
        for (int d = 0; d < 32; ++d) { float x = ks[r * 33 + d]; ss += x * x; }
        float inv = 1.0f / fmaxf(sqrtf(ss), 1e-12f);
#pragma unroll
        for (int d = 0; d < 32; ++d) ks[r * 33 + d] *= inv;
    } else if (tid < 192) {
        int n = tid - 128;
        int wi = win & 63;
        int hh = ((wi >> 3) << 3) + (n >> 3);
        int ww = ((wi & 7) << 3) + (n & 7);
        int gh = (hh < 56) ? 0 : ((hh < 60) ? 1 : 2);
        int gw = (ww < 56) ? 0 : ((ww < 60) ? 1 : 2);
        grp[n] = gh * 3 + gw;
    }
    __syncthreads();

    const float scale = expf(fminf(logit_scale[h], 4.6051701859880914f)); // log(100)

    // logits: each thread computes attn[i][j0..j0+15]
    {
        int i  = tid >> 2;
        int j0 = (tid & 3) << 4;
        float qreg[32];
#pragma unroll
        for (int d = 0; d < 32; ++d) qreg[d] = qs[i * 33 + d];
        int gi = grp[i];
        const float* rpb = g_rpb + h * 4096 + i * 64 + j0;
#pragma unroll 4
        for (int jj = 0; jj < 16; ++jj) {
            int j = j0 + jj;
            float dot = 0.f;
#pragma unroll
            for (int d = 0; d < 32; ++d) dot += qreg[d] * ks[j * 33 + d];
            float v = scale * dot + rpb[jj] + ((gi == grp[j]) ? 0.f : -100.0f);
            at[i * 65 + j] = v;
        }
    }
    __syncthreads();

    // softmax over rows
    if (tid < 64) {
        float m = -1e30f;
        for (int j = 0; j < 64; ++j) m = fmaxf(m, at[tid * 65 + j]);
        float s = 0.f;
        for (int j = 0; j < 64; ++j) {
            float e = expf(at[tid * 65 + j] - m);
            at[tid * 65 + j] = e;
            s += e;
        }
        float inv = 1.0f / s;
        for (int j = 0; j < 64; ++j) at[tid * 65 + j] *= inv;
    }
    __syncthreads();

    // out = attn @ v : each thread computes out[i][c0..c0+7]
    {
        int i  = tid >> 2;
        int c0 = (tid & 3) << 3;
        float acc[8];
#pragma unroll
        for (int d = 0; d < 8; ++d) acc[d] = 0.f;
        for (int j = 0; j < 64; ++j) {
            float a = at[i * 65 + j];
#pragma unroll
            for (int d = 0; d < 8; ++d) acc[d] += a * vs[j * 33 + c0 + d];
        }
        float* op = out + (size_t)(t0 + i) * 256 + h * 32 + c0;
#pragma unroll
        for (int d = 0; d < 8; ++d) op[d] = acc[d];
    }
}

// ---------------------------------------------------------------------------
// out[row] = res[row] + LayerNorm(xin[row]) * g + b     (C = 256, block/row)
// ---------------------------------------------------------------------------
__global__ __launch_bounds__(256)
void ln_add_kernel(const float* __restrict__ res, const float* __restrict__ xin,
                   const float* __restrict__ g, const float* __restrict__ b,
                   float* __restrict__ out) {
    __shared__ float red[256];
    const int row = blockIdx.x;
    const int t = threadIdx.x;
    const size_t base = (size_t)row * 256;
    float v = xin[base + t];
    red[t] = v;
    __syncthreads();
    for (int s = 128; s > 0; s >>= 1) {
        if (t < s) red[t] += red[t + s];
        __syncthreads();
    }
    float mean = red[0] * (1.0f / 256.0f);
    __syncthreads();
    float d = v - mean;
    red[t] = d * d;
    __syncthreads();
    for (int s = 128; s > 0; s >>= 1) {
        if (t < s) red[t] += red[t + s];
        __syncthreads();
    }
    float var = red[0] * (1.0f / 256.0f);
    out[base + t] = res[base + t] + d * rsqrtf(var + 1e-5f) * g[t] + b[t];
}

// ---------------------------------------------------------------------------
// launch
// ---------------------------------------------------------------------------
extern "C" void kernel_launch(void* const* d_in, const int* in_sizes, int n_in,
                              void* d_out, int out_size) {
    const float* x      = (const float*)d_in[0];
    const float* qkv_w  = (const float*)d_in[1];
    const float* q_bias = (const float*)d_in[2];
    const float* v_bias = (const float*)d_in[3];
    const float* lscale = (const float*)d_in[4];
    const float* cpb_w1 = (const float*)d_in[5];
    const float* cpb_b1 = (const float*)d_in[6];
    const float* cpb_w2 = (const float*)d_in[7];
    const float* proj_w = (const float*)d_in[8];
    const float* proj_b = (const float*)d_in[9];
    const float* n1g    = (const float*)d_in[10];
    const float* n1b    = (const float*)d_in[11];
    const float* n2g    = (const float*)d_in[12];
    const float* n2b    = (const float*)d_in[13];
    const float* fc1_w  = (const float*)d_in[14];
    const float* fc1_b  = (const float*)d_in[15];
    const float* fc2_w  = (const float*)d_in[16];
    const float* fc2_b  = (const float*)d_in[17];
    float* out = (float*)d_out;

    float *qkv, *attnout, *projimg, *x1, *hbuf, *mlp;
    cudaGetSymbolAddress((void**)&qkv,     g_qkv);
    cudaGetSymbolAddress((void**)&attnout, g_attnout);
    cudaGetSymbolAddress((void**)&projimg, g_projimg);
    cudaGetSymbolAddress((void**)&x1,      g_x1);
    cudaGetSymbolAddress((void**)&hbuf,    g_h);
    cudaGetSymbolAddress((void**)&mlp,     g_mlp);

    // 1) CPB bias table + rpb
    cpb_table_kernel<<<225, 256>>>(cpb_w1, cpb_b1, cpb_w2);
    rpb_kernel<<<(NH * NTOK * NTOK + 255) / 256, 256>>>();

    // 2) QKV GEMM (gathers shifted-window rows from x directly)
    {
        dim3 grid(3 * CDIM / 128, MROWS / 128);
        sgemm_kernel<1, 0, 1, 0><<<grid, 256>>>(x, qkv_w, q_bias, v_bias, qkv,
                                                MROWS, 3 * CDIM, CDIM);
    }

    // 3) fused window attention
    attn_kernel<<<(MROWS / NTOK) * NH, 256>>>(qkv, lscale, attnout);

    // 4) proj GEMM, scatter rows back to image order
    {
        dim3 grid(CDIM / 128, MROWS / 128);
        sgemm_kernel<0, 1, 0, 0><<<grid, 256>>>(attnout, proj_w, proj_b, nullptr,
                                                projimg, MROWS, CDIM, CDIM);
    }

    // 5) x1 = x + LN(proj)
    ln_add_kernel<<<MROWS, 256>>>(x, projimg, n1g, n1b, x1);

    // 6) fc1 + exact GELU
    {
        dim3 grid(HID / 128, MROWS / 128);
        sgemm_kernel<0, 0, 0, 1><<<grid, 256>>>(x1, fc1_w, fc1_b, nullptr, hbuf,
                                                MROWS, HID, CDIM);
    }

    // 7) fc2
    {
        dim3 grid(CDIM / 128, MROWS / 128);
        sgemm_kernel<0, 0, 0, 0><<<grid, 256>>>(hbuf, fc2_w, fc2_b, nullptr, mlp,
                                                MROWS, CDIM, HID);
    }

    // 8) out = x1 + LN(mlp)
    ln_add_kernel<<<MROWS, 256>>>(x1, mlp, n2g, n2b, out);
}

// round 4
// speedup vs baseline: 3.2643x; 3.2643x over previous
#include <cuda_runtime.h>
#include <math.h>
#include <stdint.h>

// ---------------------------------------------------------------------------
// Problem constants
// ---------------------------------------------------------------------------
#define BATCH   32
#define HRES    64
#define WRES    64
#define CDIM    256
#define WS      8
#define SHIFT   4
#define NH      8
#define NTOK    64
#define HD      32
#define HID     1024
#define CPB_HID 512
#define MROWS   (BATCH * HRES * WRES)   // 131072

// ---------------------------------------------------------------------------
// Scratch (allocation-free: __device__ globals)
// ---------------------------------------------------------------------------
__device__ float g_qkv[MROWS * 3 * CDIM];
__device__ float g_attnout[MROWS * CDIM];
__device__ float g_projimg[MROWS * CDIM];
__device__ float g_x1[MROWS * CDIM];
__device__ float g_h[MROWS * HID];
__device__ float g_mlp[MROWS * CDIM];
__device__ float g_bias_table[225 * NH];
__device__ float g_rpb[NH * NTOK * NTOK];

// ---------------------------------------------------------------------------
// shift+window permutation (gather for QKV A-rows, scatter for proj C-rows)
// ---------------------------------------------------------------------------
__device__ __forceinline__ int permrow(int t) {
    int b   = t >> 12;
    int loc = t & 4095;
    int win = loc >> 6;
    int n   = loc & 63;
    int sh = ((win >> 3) << 3) + (n >> 3);
    int sw = ((win & 7) << 3) + (n & 7);
    int h = (sh + SHIFT) & 63;
    int w = (sw + SHIFT) & 63;
    return (b << 12) + (h << 6) + w;
}

// ---------------------------------------------------------------------------
// CPB table + rpb
// ---------------------------------------------------------------------------
__device__ __forceinline__ float cpb_feat(int v) {
    float tv = (float)v * (8.0f / 7.0f);
    float s  = (tv > 0.f) ? 1.f : ((tv < 0.f) ? -1.f : 0.f);
    return s * log2f(fabsf(tv) + 1.0f) * (1.0f / 3.0f);
}

__global__ __launch_bounds__(256)
void cpb_table_kernel(const float* __restrict__ w1, const float* __restrict__ b1,
                      const float* __restrict__ w2) {
    int p  = blockIdx.x;
    int iy = p / 15, ix = p % 15;
    float fy = cpb_feat(iy - 7);
    float fx = cpb_feat(ix - 7);
    int t = threadIdx.x;
    float acc[NH];
#pragma unroll
    for (int hh = 0; hh < NH; ++hh) acc[hh] = 0.f;
    for (int j = t; j < CPB_HID; j += 256) {
        float hmid = fy * w1[2 * j] + fx * w1[2 * j + 1] + b1[j];
        hmid = fmaxf(hmid, 0.f);
#pragma unroll
        for (int hh = 0; hh < NH; ++hh) acc[hh] += hmid * w2[hh * CPB_HID + j];
    }
    __shared__ float red[256];
    for (int hh = 0; hh < NH; ++hh) {
        red[t] = acc[hh];
        __syncthreads();
        for (int s = 128; s > 0; s >>= 1) {
            if (t < s) red[t] += red[t + s];
            __syncthreads();
        }
        if (t == 0) g_bias_table[p * NH + hh] = red[0];
        __syncthreads();
    }
}

__global__ __launch_bounds__(256)
void rpb_kernel() {
    int idx = blockIdx.x * 256 + threadIdx.x;
    if (idx >= NH * NTOK * NTOK) return;
    int h   = idx >> 12;
    int rem = idx & 4095;
    int i = rem >> 6, j = rem & 63;
    int ri = i >> 3, ci = i & 7, rj = j >> 3, cj = j & 7;
    int p = (ri - rj + 7) * 15 + (ci - cj + 7);
    float v = g_bias_table[p * NH + h];
    g_rpb[idx] = 16.0f / (1.0f + expf(-v));
}

// ---------------------------------------------------------------------------
// TF32 tensor-core GEMM: C[M,N] = A[M,K] @ W[N,K]^T + bias
// 128x128 block tile, BK=16, 256 threads (8 warps, 4(m) x 2(n)), warp 32x64.
// mma.sync.m16n8k8.tf32. Register-double-buffered global loads.
// RA: permute A rows; RC: permute C rows; BIASM 1: qkv concat; ACT 1: GELU.
// ---------------------------------------------------------------------------
#define BKP 20   // smem row stride (floats): conflict-free fragment loads

__device__ __forceinline__ uint32_t f2tf32(float f) {
    uint32_t r;
    asm("cvt.rna.tf32.f32 %0, %1;" : "=r"(r) : "f"(f));
    return r;
}

__device__ __forceinline__ void mma_tf32(float* c, const uint32_t* a, const uint32_t* b) {
    asm volatile(
        "mma.sync.aligned.m16n8k8.row.col.f32.tf32.tf32.f32 "
        "{%0,%1,%2,%3}, {%4,%5,%6,%7}, {%8,%9}, {%0,%1,%2,%3};"
        : "+f"(c[0]), "+f"(c[1]), "+f"(c[2]), "+f"(c[3])
        : "r"(a[0]), "r"(a[1]), "r"(a[2]), "r"(a[3]), "r"(b[0]), "r"(b[1]));
}

template <int RA, int RC, int BIASM, int ACT>
__global__ __launch_bounds__(256)
void tgemm_kernel(const float* __restrict__ A, const float* __restrict__ W,
                  const float* __restrict__ b0, const float* __restrict__ b1,
                  float* __restrict__ C, int M, int N, int K) {
    __shared__ float As[128 * BKP];
    __shared__ float Ws[128 * BKP];

    const int tid  = threadIdx.x;
    const int brow = blockIdx.y * 128;
    const int bcol = blockIdx.x * 128;

    // ---- global load mapping: each thread owns rows lrow0 / lrow0+64, 4 cols
    const int lrow0 = tid >> 2;            // 0..63
    const int lrow1 = lrow0 + 64;
    const int lcol  = (tid & 3) << 2;      // 0,4,8,12
    int ar0 = brow + lrow0, ar1 = brow + lrow1;
    if (RA) { ar0 = permrow(ar0); ar1 = permrow(ar1); }
    const float* A0 = A + (size_t)ar0 * K + lcol;
    const float* A1 = A + (size_t)ar1 * K + lcol;
    const float* W0 = W + (size_t)(bcol + lrow0) * K + lcol;
    const float* W1 = W + (size_t)(bcol + lrow1) * K + lcol;

    // ---- warp tiling
    const int lane   = tid & 31;
    const int wid    = tid >> 5;
    const int warp_m = wid & 3;            // 0..3 -> m0 = warp_m*32
    const int warp_n = wid >> 2;           // 0..1 -> n0 = warp_n*64
    const int qr = lane >> 2;              // 0..7
    const int qc = lane & 3;               // 0..3
    const float* Asm = As + (warp_m * 32 + qr) * BKP + qc;
    const float* Wsm = Ws + (warp_n * 64 + qr) * BKP + qc;

    float acc[2][8][4];
#pragma unroll
    for (int mi = 0; mi < 2; ++mi)
#pragma unroll
        for (int ni = 0; ni < 8; ++ni)
#pragma unroll
            for (int e = 0; e < 4; ++e) acc[mi][ni][e] = 0.f;

    float4 av0 = *reinterpret_cast<const float4*>(A0);
    float4 av1 = *reinterpret_cast<const float4*>(A1);
    float4 wv0 = *reinterpret_cast<const float4*>(W0);
    float4 wv1 = *reinterpret_cast<const float4*>(W1);

    for (int kt = 0; kt < K; kt += 16) {
        __syncthreads();
        {
            float* pa0 = As + lrow0 * BKP + lcol;
            float* pa1 = As + lrow1 * BKP + lcol;
            float* pw0 = Ws + lrow0 * BKP + lcol;
            float* pw1 = Ws + lrow1 * BKP + lcol;
            pa0[0] = __uint_as_float(f2tf32(av0.x)); pa0[1] = __uint_as_float(f2tf32(av0.y));
            pa0[2] = __uint_as_float(f2tf32(av0.z)); pa0[3] = __uint_as_float(f2tf32(av0.w));
            pa1[0] = __uint_as_float(f2tf32(av1.x)); pa1[1] = __uint_as_float(f2tf32(av1.y));
            pa1[2] = __uint_as_float(f2tf32(av1.z)); pa1[3] = __uint_as_float(f2tf32(av1.w));
            pw0[0] = __uint_as_float(f2tf32(wv0.x)); pw0[1] = __uint_as_float(f2tf32(wv0.y));
            pw0[2] = __uint_as_float(f2tf32(wv0.z)); pw0[3] = __uint_as_float(f2tf32(wv0.w));
            pw1[0] = __uint_as_float(f2tf32(wv1.x)); pw1[1] = __uint_as_float(f2tf32(wv1.y));
            pw1[2] = __uint_as_float(f2tf32(wv1.z)); pw1[3] = __uint_as_float(f2tf32(wv1.w));
        }
        __syncthreads();
        if (kt + 16 < K) {
            av0 = *reinterpret_cast<const float4*>(A0 + kt + 16);
            av1 = *reinterpret_cast<const float4*>(A1 + kt + 16);
            wv0 = *reinterpret_cast<const float4*>(W0 + kt + 16);
            wv1 = *reinterpret_cast<const float4*>(W1 + kt + 16);
        }
#pragma unroll
        for (int ks = 0; ks < 2; ++ks) {
            const int kk = ks * 8;
            uint32_t afr[2][4];
#pragma unroll
            for (int mi = 0; mi < 2; ++mi) {
                const float* p = Asm + mi * 16 * BKP + kk;
                afr[mi][0] = __float_as_uint(p[0]);
                afr[mi][1] = __float_as_uint(p[8 * BKP]);
                afr[mi][2] = __float_as_uint(p[4]);
                afr[mi][3] = __float_as_uint(p[8 * BKP + 4]);
            }
            uint32_t bfr[8][2];
#pragma unroll
            for (int ni = 0; ni < 8; ++ni) {
                const float* p = Wsm + ni * 8 * BKP + kk;
                bfr[ni][0] = __float_as_uint(p[0]);
                bfr[ni][1] = __float_as_uint(p[4]);
            }
#pragma unroll
            for (int mi = 0; mi < 2; ++mi)
#pragma unroll
                for (int ni = 0; ni < 8; ++ni)
                    mma_tf32(acc[mi][ni], afr[mi], bfr[ni]);
        }
    }

    // ---- epilogue
#pragma unroll
    for (int mi = 0; mi < 2; ++mi) {
        int r0 = brow + warp_m * 32 + mi * 16 + qr;
        int r1 = r0 + 8;
        int cr0 = RC ? permrow(r0) : r0;
        int cr1 = RC ? permrow(r1) : r1;
        float* C0 = C + (size_t)cr0 * N;
        float* C1 = C + (size_t)cr1 * N;
#pragma unroll
        for (int ni = 0; ni < 8; ++ni) {
            int col = bcol + warp_n * 64 + ni * 8 + qc * 2;
            float bv0, bv1;
            if (BIASM == 0) {
                bv0 = b0[col]; bv1 = b0[col + 1];
            } else {
                bv0 = (col < 256) ? b0[col] : ((col < 512) ? 0.f : b1[col - 512]);
                int c1i = col + 1;
                bv1 = (c1i < 256) ? b0[c1i] : ((c1i < 512) ? 0.f : b1[c1i - 512]);
            }
            float v00 = acc[mi][ni][0] + bv0;
            float v01 = acc[mi][ni][1] + bv1;
            float v10 = acc[mi][ni][2] + bv0;
            float v11 = acc[mi][ni][3] + bv1;
            if (ACT == 1) {
                v00 = 0.5f * v00 * (1.0f + erff(v00 * 0.70710678118654752f));
                v01 = 0.5f * v01 * (1.0f + erff(v01 * 0.70710678118654752f));
                v10 = 0.5f * v10 * (1.0f + erff(v10 * 0.70710678118654752f));
                v11 = 0.5f * v11 * (1.0f + erff(v11 * 0.70710678118654752f));
            }
            *reinterpret_cast<float2*>(C0 + col) = make_float2(v00, v01);
            *reinterpret_cast<float2*>(C1 + col) = make_float2(v10, v11);
        }
    }
}

// ---------------------------------------------------------------------------
// Fused window attention
// ---------------------------------------------------------------------------
__global__ __launch_bounds__(256)
void attn_kernel(const float* __restrict__ qkv, const float* __restrict__ logit_scale,
                 float* __restrict__ out) {
    __shared__ float qs[NTOK * 33];
    __shared__ float ks[NTOK * 33];
    __shared__ float vs[NTOK * 33];
    __shared__ float at[NTOK * 65];
    __shared__ int   grp[NTOK];

    const int blk = blockIdx.x;
    const int win = blk >> 3;
    const int h   = blk & 7;
    const int tid = threadIdx.x;
    const int t0  = win << 6;

    for (int e4 = tid; e4 < 1536; e4 += 256) {
        int tensor = e4 >> 9;
        int rem = e4 & 511;
        int n = rem >> 3;
        int hd4 = rem & 7;
        float4 val = *reinterpret_cast<const float4*>(
            qkv + (size_t)(t0 + n) * 768 + tensor * 256 + h * 32 + (hd4 << 2));
        float* dst = (tensor == 0 ? qs : (tensor == 1 ? ks : vs)) + n * 33 + (hd4 << 2);
        dst[0] = val.x; dst[1] = val.y; dst[2] = val.z; dst[3] = val.w;
    }
    __syncthreads();

    if (tid < 64) {
        float ss = 0.f;
#pragma unroll
        for (int d = 0; d < 32; ++d) { float x = qs[tid * 33 + d]; ss += x * x; }
        float inv = 1.0f / fmaxf(sqrtf(ss), 1e-12f);
#pragma unroll
        for (int d = 0; d < 32; ++d) qs[tid * 33 + d] *= inv;
    } else if (tid < 128) {
        int r = tid - 64;
        float ss = 0.f;
#pragma unroll
        for (int d = 0; d < 32; ++d) { float x = ks[r * 33 + d]; ss += x * x; }
        float inv = 1.0f / fmaxf(sqrtf(ss), 1e-12f);
#pragma unroll
        for (int d = 0; d < 32; ++d) ks[r * 33 + d] *= inv;
    } else if (tid < 192) {
        int n = tid - 128;
        int wi = win & 63;
        int hh = ((wi >> 3) << 3) + (n >> 3);
        int ww = ((wi & 7) << 3) + (n & 7);
        int gh = (hh < 56) ? 0 : ((hh < 60) ? 1 : 2);
        int gw = (ww < 56) ? 0 : ((ww < 60) ? 1 : 2);
        grp[n] = gh * 3 + gw;
    }
    __syncthreads();

    const float scale = expf(fminf(logit_scale[h], 4.6051701859880914f));

    {
        int i  = tid >> 2;
        int j0 = (tid & 3) << 4;
        float qreg[32];
#pragma unroll
        for (int d = 0; d < 32; ++d) qreg[d] = qs[i * 33 + d];
        int gi = grp[i];
        const float* rpb = g_rpb + h * 4096 + i * 64 + j0;
#pragma unroll 4
        for (int jj = 0; jj < 16; ++jj) {
            int j = j0 + jj;
            float dot = 0.f;
#pragma unroll
            for (int d = 0; d < 32; ++d) dot += qreg[d] * ks[j * 33 + d];
            float v = scale * dot + rpb[jj] + ((gi == grp[j]) ? 0.f : -100.0f);
            at[i * 65 + j] = v;
        }
    }
    __syncthreads();

    if (tid < 64) {
        float m = -1e30f;
        for (int j = 0; j < 64; ++j) m = fmaxf(m, at[tid * 65 + j]);
        float s = 0.f;
        for (int j = 0; j < 64; ++j) {
            float e = expf(at[tid * 65 + j] - m);
            at[tid * 65 + j] = e;
            s += e;
        }
        float inv = 1.0f / s;
        for (int j = 0; j < 64; ++j) at[tid * 65 + j] *= inv;
    }
    __syncthreads();

    {
        int i  = tid >> 2;
        int c0 = (tid & 3) << 3;
        float acc[8];
#pragma unroll
        for (int d = 0; d < 8; ++d) acc[d] = 0.f;
        for (int j = 0; j < 64; ++j) {
            float a = at[i * 65 + j];
#pragma unroll
            for (int d = 0; d < 8; ++d) acc[d] += a * vs[j * 33 + c0 + d];
        }
        float* op = out + (size_t)(t0 + i) * 256 + h * 32 + c0;
#pragma unroll
        for (int d = 0; d < 8; ++d) op[d] = acc[d];
    }
}

// ---------------------------------------------------------------------------
// out[row] = res[row] + LayerNorm(xin[row]) * g + b
// ---------------------------------------------------------------------------
__global__ __launch_bounds__(256)
void ln_add_kernel(const float* __restrict__ res, const float* __restrict__ xin,
                   const float* __restrict__ g, const float* __restrict__ b,
                   float* __restrict__ out) {
    __shared__ float red[256];
    const int row = blockIdx.x;
    const int t = threadIdx.x;
    const size_t base = (size_t)row * 256;
    float v = xin[base + t];
    red[t] = v;
    __syncthreads();
    for (int s = 128; s > 0; s >>= 1) {
        if (t < s) red[t] += red[t + s];
        __syncthreads();
    }
    float mean = red[0] * (1.0f / 256.0f);
    __syncthreads();
    float d = v - mean;
    red[t] = d * d;
    __syncthreads();
    for (int s = 128; s > 0; s >>= 1) {
        if (t < s) red[t] += red[t + s];
        __syncthreads();
    }
    float var = red[0] * (1.0f / 256.0f);
    out[base + t] = res[base + t] + d * rsqrtf(var + 1e-5f) * g[t] + b[t];
}

// ---------------------------------------------------------------------------
// launch
// ---------------------------------------------------------------------------
extern "C" void kernel_launch(void* const* d_in, const int* in_sizes, int n_in,
                              void* d_out, int out_size) {
    const float* x      = (const float*)d_in[0];
    const float* qkv_w  = (const float*)d_in[1];
    const float* q_bias = (const float*)d_in[2];
    const float* v_bias = (const float*)d_in[3];
    const float* lscale = (const float*)d_in[4];
    const float* cpb_w1 = (const float*)d_in[5];
    const float* cpb_b1 = (const float*)d_in[6];
    const float* cpb_w2 = (const float*)d_in[7];
    const float* proj_w = (const float*)d_in[8];
    const float* proj_b = (const float*)d_in[9];
    const float* n1g    = (const float*)d_in[10];
    const float* n1b    = (const float*)d_in[11];
    const float* n2g    = (const float*)d_in[12];
    const float* n2b    = (const float*)d_in[13];
    const float* fc1_w  = (const float*)d_in[14];
    const float* fc1_b  = (const float*)d_in[15];
    const float* fc2_w  = (const float*)d_in[16];
    const float* fc2_b  = (const float*)d_in[17];
    float* out = (float*)d_out;

    float *qkv, *attnout, *projimg, *x1, *hbuf, *mlp;
    cudaGetSymbolAddress((void**)&qkv,     g_qkv);
    cudaGetSymbolAddress((void**)&attnout, g_attnout);
    cudaGetSymbolAddress((void**)&projimg, g_projimg);
    cudaGetSymbolAddress((void**)&x1,      g_x1);
    cudaGetSymbolAddress((void**)&hbuf,    g_h);
    cudaGetSymbolAddress((void**)&mlp,     g_mlp);

    cpb_table_kernel<<<225, 256>>>(cpb_w1, cpb_b1, cpb_w2);
    rpb_kernel<<<(NH * NTOK * NTOK + 255) / 256, 256>>>();

    {   // QKV (gather shifted-window rows from x)
        dim3 grid(3 * CDIM / 128, MROWS / 128);
        tgemm_kernel<1, 0, 1, 0><<<grid, 256>>>(x, qkv_w, q_bias, v_bias, qkv,
                                                MROWS, 3 * CDIM, CDIM);
    }

    attn_kernel<<<(MROWS / NTOK) * NH, 256>>>(qkv, lscale, attnout);

    {   // proj (scatter rows back to image order)
        dim3 grid(CDIM / 128, MROWS / 128);
        tgemm_kernel<0, 1, 0, 0><<<grid, 256>>>(attnout, proj_w, proj_b, nullptr,
                                                projimg, MROWS, CDIM, CDIM);
    }

    ln_add_kernel<<<MROWS, 256>>>(x, projimg, n1g, n1b, x1);

    {   // fc1 + exact GELU
        dim3 grid(HID / 128, MROWS / 128);
        tgemm_kernel<0, 0, 0, 1><<<grid, 256>>>(x1, fc1_w, fc1_b, nullptr, hbuf,
                                                MROWS, HID, CDIM);
    }

    {   // fc2
        dim3 grid(CDIM / 128, MROWS / 128);
        tgemm_kernel<0, 0, 0, 0><<<grid, 256>>>(hbuf, fc2_w, fc2_b, nullptr, mlp,
                                                MROWS, CDIM, HID);
    }

    ln_add_kernel<<<MROWS, 256>>>(x1, mlp, n2g, n2b, out);
}

// round 8
// speedup vs baseline: 3.7300x; 1.1427x over previous
#include <cuda_runtime.h>
#include <math.h>
#include <stdint.h>

// ---------------------------------------------------------------------------
// Problem constants
// ---------------------------------------------------------------------------
#define BATCH   32
#define HRES    64
#define WRES    64
#define CDIM    256
#define WS      8
#define SHIFT   4
#define NH      8
#define NTOK    64
#define HD      32
#define HID     1024
#define CPB_HID 512
#define MROWS   (BATCH * HRES * WRES)   // 131072

// ---------------------------------------------------------------------------
// Scratch (allocation-free: __device__ globals)
// ---------------------------------------------------------------------------
__device__ float g_qkv[MROWS * 3 * CDIM];
__device__ float g_attnout[MROWS * CDIM];
__device__ float g_projimg[MROWS * CDIM];
__device__ float g_x1[MROWS * CDIM];
__device__ float g_h[MROWS * HID];
__device__ float g_mlp[MROWS * CDIM];
__device__ float g_bias_table[225 * NH];
__device__ float g_rpb[NH * NTOK * NTOK];

// ---------------------------------------------------------------------------
// shift+window permutation (gather for QKV A-rows, scatter for proj C-rows)
// ---------------------------------------------------------------------------
__device__ __forceinline__ int permrow(int t) {
    int b   = t >> 12;
    int loc = t & 4095;
    int win = loc >> 6;
    int n   = loc & 63;
    int sh = ((win >> 3) << 3) + (n >> 3);
    int sw = ((win & 7) << 3) + (n & 7);
    int h = (sh + SHIFT) & 63;
    int w = (sw + SHIFT) & 63;
    return (b << 12) + (h << 6) + w;
}

// ---------------------------------------------------------------------------
// CPB table + rpb
// ---------------------------------------------------------------------------
__device__ __forceinline__ float cpb_feat(int v) {
    float tv = (float)v * (8.0f / 7.0f);
    float s  = (tv > 0.f) ? 1.f : ((tv < 0.f) ? -1.f : 0.f);
    return s * log2f(fabsf(tv) + 1.0f) * (1.0f / 3.0f);
}

__global__ __launch_bounds__(256)
void cpb_table_kernel(const float* __restrict__ w1, const float* __restrict__ b1,
                      const float* __restrict__ w2) {
    int p  = blockIdx.x;
    int iy = p / 15, ix = p % 15;
    float fy = cpb_feat(iy - 7);
    float fx = cpb_feat(ix - 7);
    int t = threadIdx.x;
    float acc[NH];
#pragma unroll
    for (int hh = 0; hh < NH; ++hh) acc[hh] = 0.f;
    for (int j = t; j < CPB_HID; j += 256) {
        float hmid = fy * w1[2 * j] + fx * w1[2 * j + 1] + b1[j];
        hmid = fmaxf(hmid, 0.f);
#pragma unroll
        for (int hh = 0; hh < NH; ++hh) acc[hh] += hmid * w2[hh * CPB_HID + j];
    }
    __shared__ float red[256];
    for (int hh = 0; hh < NH; ++hh) {
        red[t] = acc[hh];
        __syncthreads();
        for (int s = 128; s > 0; s >>= 1) {
            if (t < s) red[t] += red[t + s];
            __syncthreads();
        }
        if (t == 0) g_bias_table[p * NH + hh] = red[0];
        __syncthreads();
    }
}

__global__ __launch_bounds__(256)
void rpb_kernel() {
    int idx = blockIdx.x * 256 + threadIdx.x;
    if (idx >= NH * NTOK * NTOK) return;
    int h   = idx >> 12;
    int rem = idx & 4095;
    int i = rem >> 6, j = rem & 63;
    int ri = i >> 3, ci = i & 7, rj = j >> 3, cj = j & 7;
    int p = (ri - rj + 7) * 15 + (ci - cj + 7);
    float v = g_bias_table[p * NH + h];
    g_rpb[idx] = 16.0f / (1.0f + expf(-v));
}

// ---------------------------------------------------------------------------
// TF32 tensor-core GEMM, double-buffered smem (1 sync per K-step)
// ---------------------------------------------------------------------------
#define BKP 20

__device__ __forceinline__ uint32_t f2tf32(float f) {
    uint32_t r;
    asm("cvt.rna.tf32.f32 %0, %1;" : "=r"(r) : "f"(f));
    return r;
}

__device__ __forceinline__ void mma_tf32(float* c, const uint32_t* a, const uint32_t* b) {
    asm volatile(
        "mma.sync.aligned.m16n8k8.row.col.f32.tf32.tf32.f32 "
        "{%0,%1,%2,%3}, {%4,%5,%6,%7}, {%8,%9}, {%0,%1,%2,%3};"
        : "+f"(c[0]), "+f"(c[1]), "+f"(c[2]), "+f"(c[3])
        : "r"(a[0]), "r"(a[1]), "r"(a[2]), "r"(a[3]), "r"(b[0]), "r"(b[1]));
}

__device__ __forceinline__ void stage_store(float* Asb, float* Wsb,
                                            int lrow0, int lrow1, int lcol,
                                            const float4& av0, const float4& av1,
                                            const float4& wv0, const float4& wv1) {
    float* pa0 = Asb + lrow0 * BKP + lcol;
    float* pa1 = Asb + lrow1 * BKP + lcol;
    float* pw0 = Wsb + lrow0 * BKP + lcol;
    float* pw1 = Wsb + lrow1 * BKP + lcol;
    pa0[0] = __uint_as_float(f2tf32(av0.x)); pa0[1] = __uint_as_float(f2tf32(av0.y));
    pa0[2] = __uint_as_float(f2tf32(av0.z)); pa0[3] = __uint_as_float(f2tf32(av0.w));
    pa1[0] = __uint_as_float(f2tf32(av1.x)); pa1[1] = __uint_as_float(f2tf32(av1.y));
    pa1[2] = __uint_as_float(f2tf32(av1.z)); pa1[3] = __uint_as_float(f2tf32(av1.w));
    pw0[0] = __uint_as_float(f2tf32(wv0.x)); pw0[1] = __uint_as_float(f2tf32(wv0.y));
    pw0[2] = __uint_as_float(f2tf32(wv0.z)); pw0[3] = __uint_as_float(f2tf32(wv0.w));
    pw1[0] = __uint_as_float(f2tf32(wv1.x)); pw1[1] = __uint_as_float(f2tf32(wv1.y));
    pw1[2] = __uint_as_float(f2tf32(wv1.z)); pw1[3] = __uint_as_float(f2tf32(wv1.w));
}

template <int RA, int RC, int BIASM, int ACT>
__global__ __launch_bounds__(256)
void tgemm_kernel(const float* __restrict__ A, const float* __restrict__ W,
                  const float* __restrict__ b0, const float* __restrict__ b1,
                  float* __restrict__ C, int M, int N, int K) {
    __shared__ float As[2][128 * BKP];
    __shared__ float Ws[2][128 * BKP];

    const int tid  = threadIdx.x;
    const int brow = blockIdx.y * 128;
    const int bcol = blockIdx.x * 128;

    const int lrow0 = tid >> 2;
    const int lrow1 = lrow0 + 64;
    const int lcol  = (tid & 3) << 2;
    int ar0 = brow + lrow0, ar1 = brow + lrow1;
    if (RA) { ar0 = permrow(ar0); ar1 = permrow(ar1); }
    const float* A0 = A + (size_t)ar0 * K + lcol;
    const float* A1 = A + (size_t)ar1 * K + lcol;
    const float* W0 = W + (size_t)(bcol + lrow0) * K + lcol;
    const float* W1 = W + (size_t)(bcol + lrow1) * K + lcol;

    const int lane   = tid & 31;
    const int wid    = tid >> 5;
    const int warp_m = wid & 3;
    const int warp_n = wid >> 2;
    const int qr = lane >> 2;
    const int qc = lane & 3;
    const int aoff = (warp_m * 32 + qr) * BKP + qc;
    const int woff = (warp_n * 64 + qr) * BKP + qc;

    float acc[2][8][4];
#pragma unroll
    for (int mi = 0; mi < 2; ++mi)
#pragma unroll
        for (int ni = 0; ni < 8; ++ni)
#pragma unroll
            for (int e = 0; e < 4; ++e) acc[mi][ni][e] = 0.f;

    float4 av0 = *reinterpret_cast<const float4*>(A0);
    float4 av1 = *reinterpret_cast<const float4*>(A1);
    float4 wv0 = *reinterpret_cast<const float4*>(W0);
    float4 wv1 = *reinterpret_cast<const float4*>(W1);
    stage_store(As[0], Ws[0], lrow0, lrow1, lcol, av0, av1, wv0, wv1);
    __syncthreads();

    const int nstages = K >> 4;
    for (int it = 0; it < nstages; ++it) {
        const int cur = it & 1;
        const int ktn = (it + 1) << 4;
        const bool more = ktn < K;
        if (more) {
            av0 = *reinterpret_cast<const float4*>(A0 + ktn);
            av1 = *reinterpret_cast<const float4*>(A1 + ktn);
            wv0 = *reinterpret_cast<const float4*>(W0 + ktn);
            wv1 = *reinterpret_cast<const float4*>(W1 + ktn);
        }
        const float* Asm = As[cur] + aoff;
        const float* Wsm = Ws[cur] + woff;
#pragma unroll
        for (int ks = 0; ks < 2; ++ks) {
            const int kk = ks * 8;
            uint32_t afr[2][4];
#pragma unroll
            for (int mi = 0; mi < 2; ++mi) {
                const float* p = Asm + mi * 16 * BKP + kk;
                afr[mi][0] = __float_as_uint(p[0]);
                afr[mi][1] = __float_as_uint(p[8 * BKP]);
                afr[mi][2] = __float_as_uint(p[4]);
                afr[mi][3] = __float_as_uint(p[8 * BKP + 4]);
            }
            uint32_t bfr[8][2];
#pragma unroll
            for (int ni = 0; ni < 8; ++ni) {
                const float* p = Wsm + ni * 8 * BKP + kk;
                bfr[ni][0] = __float_as_uint(p[0]);
                bfr[ni][1] = __float_as_uint(p[4]);
            }
#pragma unroll
            for (int mi = 0; mi < 2; ++mi)
#pragma unroll
                for (int ni = 0; ni < 8; ++ni)
                    mma_tf32(acc[mi][ni], afr[mi], bfr[ni]);
        }
        if (more)
            stage_store(As[cur ^ 1], Ws[cur ^ 1], lrow0, lrow1, lcol, av0, av1, wv0, wv1);
        __syncthreads();
    }

    // ---- epilogue
#pragma unroll
    for (int mi = 0; mi < 2; ++mi) {
        int r0 = brow + warp_m * 32 + mi * 16 + qr;
        int r1 = r0 + 8;
        int cr0 = RC ? permrow(r0) : r0;
        int cr1 = RC ? permrow(r1) : r1;
        float* C0 = C + (size_t)cr0 * N;
        float* C1 = C + (size_t)cr1 * N;
#pragma unroll
        for (int ni = 0; ni < 8; ++ni) {
            int col = bcol + warp_n * 64 + ni * 8 + qc * 2;
            float bv0, bv1;
            if (BIASM == 0) {
                bv0 = b0[col]; bv1 = b0[col + 1];
            } else {
                bv0 = (col < 256) ? b0[col] : ((col < 512) ? 0.f : b1[col - 512]);
                int c1i = col + 1;
                bv1 = (c1i < 256) ? b0[c1i] : ((c1i < 512) ? 0.f : b1[c1i - 512]);
            }
            float v00 = acc[mi][ni][0] + bv0;
            float v01 = acc[mi][ni][1] + bv1;
            float v10 = acc[mi][ni][2] + bv0;
            float v11 = acc[mi][ni][3] + bv1;
            if (ACT == 1) {
                v00 = 0.5f * v00 * (1.0f + erff(v00 * 0.70710678118654752f));
                v01 = 0.5f * v01 * (1.0f + erff(v01 * 0.70710678118654752f));
                v10 = 0.5f * v10 * (1.0f + erff(v10 * 0.70710678118654752f));
                v11 = 0.5f * v11 * (1.0f + erff(v11 * 0.70710678118654752f));
            }
            *reinterpret_cast<float2*>(C0 + col) = make_float2(v00, v01);
            *reinterpret_cast<float2*>(C1 + col) = make_float2(v10, v11);
        }
    }
}

// ---------------------------------------------------------------------------
// Fused window attention, vectorized smem + register softmax.
// One block per (window, head), 256 threads. Thread t handles row i = t>>2
// and the 16 columns j = 4*jj + (t&3).
// ---------------------------------------------------------------------------
#define QS 36   // q/k/v row stride (floats)
#define PS 68   // prob row stride (floats)

__global__ __launch_bounds__(256)
void attn_kernel(const float* __restrict__ qkv, const float* __restrict__ logit_scale,
                 float* __restrict__ out) {
    __shared__ float qs[NTOK * QS];
    __shared__ float ks[NTOK * QS];
    __shared__ float vs[NTOK * QS];
    __shared__ float ps[NTOK * PS];
    __shared__ int   grp[NTOK];

    const int blk = blockIdx.x;
    const int win = blk >> 3;
    const int h   = blk & 7;
    const int tid = threadIdx.x;
    const int t0  = win << 6;

    // load q/k/v head slices (1536 float4)
    for (int e4 = tid; e4 < 1536; e4 += 256) {
        int tensor = e4 >> 9;
        int rem = e4 & 511;
        int n = rem >> 3;
        int hd4 = rem & 7;
        float4 val = *reinterpret_cast<const float4*>(
            qkv + (size_t)(t0 + n) * 768 + tensor * 256 + h * 32 + (hd4 << 2));
        float* dst = (tensor == 0 ? qs : (tensor == 1 ? ks : vs)) + n * QS + (hd4 << 2);
        *reinterpret_cast<float4*>(dst) = val;
    }
    if (tid < 64) {
        int wi = win & 63;
        int hh = ((wi >> 3) << 3) + (tid >> 3);
        int ww = ((wi & 7) << 3) + (tid & 7);
        int gh = (hh < 56) ? 0 : ((hh < 60) ? 1 : 2);
        int gw = (ww < 56) ? 0 : ((ww < 60) ? 1 : 2);
        grp[tid] = gh * 3 + gw;
    }
    __syncthreads();

    // l2-normalize q and k rows (128 threads, one row each)
    if (tid < 128) {
        float* base = (tid < 64 ? qs : ks) + (tid & 63) * QS;
        float4 r[8];
        float ss = 0.f;
#pragma unroll
        for (int d4 = 0; d4 < 8; ++d4) {
            r[d4] = *reinterpret_cast<const float4*>(base + (d4 << 2));
            ss += r[d4].x * r[d4].x + r[d4].y * r[d4].y
                + r[d4].z * r[d4].z + r[d4].w * r[d4].w;
        }
        float inv = 1.0f / fmaxf(sqrtf(ss), 1e-12f);
#pragma unroll
        for (int d4 = 0; d4 < 8; ++d4) {
            r[d4].x *= inv; r[d4].y *= inv; r[d4].z *= inv; r[d4].w *= inv;
            *reinterpret_cast<float4*>(base + (d4 << 2)) = r[d4];
        }
    }
    __syncthreads();

    const float scale = expf(fminf(logit_scale[h], 4.6051701859880914f));
    const int i  = tid >> 2;
    const int jq = tid & 3;
    const int wi = win & 63;
    const bool edge = ((wi >> 3) == 7) || ((wi & 7) == 7);

    // q row in registers
    float4 q4[8];
#pragma unroll
    for (int d4 = 0; d4 < 8; ++d4)
        q4[d4] = *reinterpret_cast<const float4*>(qs + i * QS + (d4 << 2));
    const int gi = grp[i];

    // logits (16 per thread, columns j = 4*jj + jq)
    float lt[16];
#pragma unroll
    for (int jj = 0; jj < 16; ++jj) {
        const int j = (jj << 2) + jq;
        const float* kr = ks + j * QS;
        float dot = 0.f;
#pragma unroll
        for (int d4 = 0; d4 < 8; ++d4) {
            float4 k4 = *reinterpret_cast<const float4*>(kr + (d4 << 2));
            dot = fmaf(q4[d4].x, k4.x, dot);
            dot = fmaf(q4[d4].y, k4.y, dot);
            dot = fmaf(q4[d4].z, k4.z, dot);
            dot = fmaf(q4[d4].w, k4.w, dot);
        }
        float v = fmaf(scale, dot, g_rpb[h * 4096 + i * 64 + j]);
        if (edge && gi != grp[j]) v -= 100.0f;
        lt[jj] = v;
    }

    // softmax across the quad (full row of 64)
    float m = lt[0];
#pragma unroll
    for (int jj = 1; jj < 16; ++jj) m = fmaxf(m, lt[jj]);
    m = fmaxf(m, __shfl_xor_sync(0xffffffffu, m, 1));
    m = fmaxf(m, __shfl_xor_sync(0xffffffffu, m, 2));
    float s = 0.f;
#pragma unroll
    for (int jj = 0; jj < 16; ++jj) { lt[jj] = __expf(lt[jj] - m); s += lt[jj]; }
    s += __shfl_xor_sync(0xffffffffu, s, 1);
    s += __shfl_xor_sync(0xffffffffu, s, 2);
    float inv = 1.0f / s;
#pragma unroll
    for (int jj = 0; jj < 16; ++jj)
        ps[i * PS + (jj << 2) + jq] = lt[jj] * inv;
    __syncthreads();

    // AV: thread computes out[i][c0..c0+7]
    {
        const int c0 = jq << 3;
        float acc[8];
#pragma unroll
        for (int e = 0; e < 8; ++e) acc[e] = 0.f;
        const float* pr = ps + i * PS;
#pragma unroll
        for (int j4 = 0; j4 < 16; ++j4) {
            float4 a4 = *reinterpret_cast<const float4*>(pr + (j4 << 2));
            float aj[4] = {a4.x, a4.y, a4.z, a4.w};
#pragma unroll
            for (int e = 0; e < 4; ++e) {
                const float* vb = vs + ((j4 << 2) + e) * QS + c0;
                float4 v0 = *reinterpret_cast<const float4*>(vb);
                float4 v1 = *reinterpret_cast<const float4*>(vb + 4);
                acc[0] = fmaf(aj[e], v0.x, acc[0]);
                acc[1] = fmaf(aj[e], v0.y, acc[1]);
                acc[2] = fmaf(aj[e], v0.z, acc[2]);
                acc[3] = fmaf(aj[e], v0.w, acc[3]);
                acc[4] = fmaf(aj[e], v1.x, acc[4]);
                acc[5] = fmaf(aj[e], v1.y, acc[5]);
                acc[6] = fmaf(aj[e], v1.z, acc[6]);
                acc[7] = fmaf(aj[e], v1.w, acc[7]);
            }
        }
        float* op = out + (size_t)(t0 + i) * 256 + h * 32 + c0;
        *reinterpret_cast<float4*>(op)     = make_float4(acc[0], acc[1], acc[2], acc[3]);
        *reinterpret_cast<float4*>(op + 4) = make_float4(acc[4], acc[5], acc[6], acc[7]);
    }
}

// ---------------------------------------------------------------------------
// out[row] = res[row] + LayerNorm(xin[row]) * g + b
// ---------------------------------------------------------------------------
__global__ __launch_bounds__(256)
void ln_add_kernel(const float* __restrict__ res, const float* __restrict__ xin,
                   const float* __restrict__ g, const float* __restrict__ b,
                   float* __restrict__ out) {
    __shared__ float red[256];
    const int row = blockIdx.x;
    const int t = threadIdx.x;
    const size_t base = (size_t)row * 256;
    float v = xin[base + t];
    red[t] = v;
    __syncthreads();
    for (int s = 128; s > 0; s >>= 1) {
        if (t < s) red[t] += red[t + s];
        __syncthreads();
    }
    float mean = red[0] * (1.0f / 256.0f);
    __syncthreads();
    float d = v - mean;
    red[t] = d * d;
    __syncthreads();
    for (int s = 128; s > 0; s >>= 1) {
        if (t < s) red[t] += red[t + s];
        __syncthreads();
    }
    float var = red[0] * (1.0f / 256.0f);
    out[base + t] = res[base + t] + d * rsqrtf(var + 1e-5f) * g[t] + b[t];
}

// ---------------------------------------------------------------------------
// launch
// ---------------------------------------------------------------------------
extern "C" void kernel_launch(void* const* d_in, const int* in_sizes, int n_in,
                              void* d_out, int out_size) {
    const float* x      = (const float*)d_in[0];
    const float* qkv_w  = (const float*)d_in[1];
    const float* q_bias = (const float*)d_in[2];
    const float* v_bias = (const float*)d_in[3];
    const float* lscale = (const float*)d_in[4];
    const float* cpb_w1 = (const float*)d_in[5];
    const float* cpb_b1 = (const float*)d_in[6];
    const float* cpb_w2 = (const float*)d_in[7];
    const float* proj_w = (const float*)d_in[8];
    const float* proj_b = (const float*)d_in[9];
    const float* n1g    = (const float*)d_in[10];
    const float* n1b    = (const float*)d_in[11];
    const float* n2g    = (const float*)d_in[12];
    const float* n2b    = (const float*)d_in[13];
    const float* fc1_w  = (const float*)d_in[14];
    const float* fc1_b  = (const float*)d_in[15];
    const float* fc2_w  = (const float*)d_in[16];
    const float* fc2_b  = (const float*)d_in[17];
    float* out = (float*)d_out;

    float *qkv, *attnout, *projimg, *x1, *hbuf, *mlp;
    cudaGetSymbolAddress((void**)&qkv,     g_qkv);
    cudaGetSymbolAddress((void**)&attnout, g_attnout);
    cudaGetSymbolAddress((void**)&projimg, g_projimg);
    cudaGetSymbolAddress((void**)&x1,      g_x1);
    cudaGetSymbolAddress((void**)&hbuf,    g_h);
    cudaGetSymbolAddress((void**)&mlp,     g_mlp);

    cpb_table_kernel<<<225, 256>>>(cpb_w1, cpb_b1, cpb_w2);
    rpb_kernel<<<(NH * NTOK * NTOK + 255) / 256, 256>>>();

    {   // QKV (gather shifted-window rows from x)
        dim3 grid(3 * CDIM / 128, MROWS / 128);
        tgemm_kernel<1, 0, 1, 0><<<grid, 256>>>(x, qkv_w, q_bias, v_bias, qkv,
                                                MROWS, 3 * CDIM, CDIM);
    }

    attn_kernel<<<(MROWS / NTOK) * NH, 256>>>(qkv, lscale, attnout);

    {   // proj (scatter rows back to image order)
        dim3 grid(CDIM / 128, MROWS / 128);
        tgemm_kernel<0, 1, 0, 0><<<grid, 256>>>(attnout, proj_w, proj_b, nullptr,
                                                projimg, MROWS, CDIM, CDIM);
    }

    ln_add_kernel<<<MROWS, 256>>>(x, projimg, n1g, n1b, x1);

    {   // fc1 + exact GELU
        dim3 grid(HID / 128, MROWS / 128);
        tgemm_kernel<0, 0, 0, 1><<<grid, 256>>>(x1, fc1_w, fc1_b, nullptr, hbuf,
                                                MROWS, HID, CDIM);
    }

    {   // fc2
        dim3 grid(CDIM / 128, MROWS / 128);
        tgemm_kernel<0, 0, 0, 0><<<grid, 256>>>(hbuf, fc2_w, fc2_b, nullptr, mlp,
                                                MROWS, CDIM, HID);
    }

    ln_add_kernel<<<MROWS, 256>>>(x1, mlp, n2g, n2b, out);
}